// round 2
// baseline (speedup 1.0000x reference)
#include <cuda_runtime.h>
#include <cuda_bf16.h>

// Problem constants (dataset is fixed: 50000 nodes, 800000 edges, 64 feats)
#define MAX_NODES 50048
#define MAX_EDGES 800000
#define SCAN_T    1024

// Scratch (allocation-free rule: __device__ globals)
__device__ int g_count[MAX_NODES];
__device__ int g_offset[MAX_NODES + 1];
__device__ int g_cursor[MAX_NODES];
__device__ int g_srow[MAX_EDGES];

__global__ void k_zero(int n) {
    int i = blockIdx.x * blockDim.x + threadIdx.x;
    if (i < n) g_count[i] = 0;
}

__global__ void k_hist(const int* __restrict__ col, int E) {
    int i = blockIdx.x * blockDim.x + threadIdx.x;
    if (i < E) atomicAdd(&g_count[col[i]], 1);
}

// Single-block exclusive scan of g_count -> g_offset / g_cursor.
// Each thread owns a contiguous chunk (~49 elems): local sum, block scan
// of the 1024 partials, then local prefix writeback. All L2-resident.
__global__ void k_scan(int n) {
    __shared__ int sh[SCAN_T];
    int t = threadIdx.x;
    int chunk = (n + SCAN_T - 1) / SCAN_T;          // 49
    int beg = t * chunk;
    int end = min(beg + chunk, n);

    int s = 0;
    for (int i = beg; i < end; i++) s += g_count[i];
    sh[t] = s;
    __syncthreads();
    // Hillis–Steele inclusive scan over 1024 partials
    #pragma unroll
    for (int off = 1; off < SCAN_T; off <<= 1) {
        int v = (t >= off) ? sh[t - off] : 0;
        __syncthreads();
        sh[t] += v;
        __syncthreads();
    }
    int excl = sh[t] - s;                            // exclusive base for my chunk
    for (int i = beg; i < end; i++) {
        int c = g_count[i];
        g_offset[i] = excl;
        g_cursor[i] = excl;
        excl += c;
    }
    if (t == SCAN_T - 1) g_offset[n] = excl;         // total == E
}

// Bucket the source node of every edge by destination (counting sort)
__global__ void k_scatter(const int* __restrict__ row, const int* __restrict__ col, int E) {
    int i = blockIdx.x * blockDim.x + threadIdx.x;
    if (i < E) {
        int c = col[i];
        int pos = atomicAdd(&g_cursor[c], 1);
        g_srow[pos] = row[i];
    }
}

// One warp per destination node; lane handles features [2*lane, 2*lane+1].
// Atomic-free segmented mean; gathers are L2-resident. 4-deep accumulators
// for memory-level parallelism.
__global__ void k_gather(const float* __restrict__ x, float* __restrict__ out, int n) {
    int warp = (blockIdx.x * blockDim.x + threadIdx.x) >> 5;
    int lane = threadIdx.x & 31;
    if (warp >= n) return;
    int start = g_offset[warp];
    int end   = g_offset[warp + 1];

    float2 a0 = make_float2(0.f, 0.f);
    float2 a1 = make_float2(0.f, 0.f);
    float2 a2 = make_float2(0.f, 0.f);
    float2 a3 = make_float2(0.f, 0.f);
    int i = start;
    for (; i + 4 <= end; i += 4) {
        int r0 = g_srow[i];
        int r1 = g_srow[i + 1];
        int r2 = g_srow[i + 2];
        int r3 = g_srow[i + 3];
        float2 v0 = *reinterpret_cast<const float2*>(x + ((size_t)r0 << 6) + (lane << 1));
        float2 v1 = *reinterpret_cast<const float2*>(x + ((size_t)r1 << 6) + (lane << 1));
        float2 v2 = *reinterpret_cast<const float2*>(x + ((size_t)r2 << 6) + (lane << 1));
        float2 v3 = *reinterpret_cast<const float2*>(x + ((size_t)r3 << 6) + (lane << 1));
        a0.x += v0.x; a0.y += v0.y;
        a1.x += v1.x; a1.y += v1.y;
        a2.x += v2.x; a2.y += v2.y;
        a3.x += v3.x; a3.y += v3.y;
    }
    for (; i < end; i++) {
        int r0 = g_srow[i];
        float2 v0 = *reinterpret_cast<const float2*>(x + ((size_t)r0 << 6) + (lane << 1));
        a0.x += v0.x; a0.y += v0.y;
    }
    int deg = end - start;
    float inv = 1.0f / (float)(deg > 0 ? deg : 1);
    float2 o = make_float2((a0.x + a1.x + a2.x + a3.x) * inv,
                           (a0.y + a1.y + a2.y + a3.y) * inv);
    *reinterpret_cast<float2*>(out + ((size_t)warp << 6) + (lane << 1)) = o;
}

extern "C" void kernel_launch(void* const* d_in, const int* in_sizes, int n_in,
                              void* d_out, int out_size) {
    const float* x    = (const float*)d_in[0];
    const int*   edge = (const int*)d_in[1];
    float*       out  = (float*)d_out;

    const int n = in_sizes[0] / 64;     // 50000
    const int E = in_sizes[1] / 2;      // 800000
    const int* row = edge;              // edge_index[0, :]
    const int* col = edge + E;          // edge_index[1, :]

    k_zero   <<<(n + 255) / 256, 256>>>(n);
    k_hist   <<<(E + 255) / 256, 256>>>(col, E);
    k_scan   <<<1, SCAN_T>>>(n);
    k_scatter<<<(E + 255) / 256, 256>>>(row, col, E);
    k_gather <<<(n + 7) / 8, 256>>>(x, out, n);     // one warp per node
}

// round 4
// speedup vs baseline: 2.5101x; 2.5101x over previous
#include <cuda_runtime.h>
#include <cuda_bf16.h>

// Problem constants (dataset is fixed: 50000 nodes, 800000 edges, 64 feats)
#define MAX_NODES 50048
#define MAX_EDGES 800000
#define SCAN_BLK  1024
#define MAX_SCAN_BLOCKS 64   // ceil(50000/1024) = 49

// Scratch (allocation-free rule: __device__ globals)
__device__ int g_count[MAX_NODES];
__device__ int g_offset[MAX_NODES + 1];
__device__ int g_cursor[MAX_NODES];
__device__ int g_srow[MAX_EDGES];
__device__ int g_blocksum[MAX_SCAN_BLOCKS];

// Vectorized zero of g_count (MAX_NODES % 4 == 0)
__global__ void k_zero(int n4) {
    int i = blockIdx.x * blockDim.x + threadIdx.x;
    if (i < n4) reinterpret_cast<int4*>(g_count)[i] = make_int4(0, 0, 0, 0);
}

// Histogram of destinations. int4-vectorized edge reads (E % 4 == 0).
__global__ void k_hist(const int* __restrict__ col, int E4) {
    int i = blockIdx.x * blockDim.x + threadIdx.x;
    if (i < E4) {
        int4 c = reinterpret_cast<const int4*>(col)[i];
        atomicAdd(&g_count[c.x], 1);
        atomicAdd(&g_count[c.y], 1);
        atomicAdd(&g_count[c.z], 1);
        atomicAdd(&g_count[c.w], 1);
    }
}

// Coalesced block reduce of g_count -> g_blocksum
__global__ void k_scanA(int n) {
    __shared__ int s_warp[32];
    int i = blockIdx.x * SCAN_BLK + threadIdx.x;
    int v = (i < n) ? g_count[i] : 0;
    #pragma unroll
    for (int o = 16; o > 0; o >>= 1) v += __shfl_down_sync(0xffffffffu, v, o);
    int wid = threadIdx.x >> 5, lane = threadIdx.x & 31;
    if (lane == 0) s_warp[wid] = v;
    __syncthreads();
    if (wid == 0) {
        int s = s_warp[lane];
        #pragma unroll
        for (int o = 16; o > 0; o >>= 1) s += __shfl_down_sync(0xffffffffu, s, o);
        if (lane == 0) g_blocksum[blockIdx.x] = s;
    }
}

// Each block: redundantly compute its global base from the 49 blocksums,
// then shuffle-based exclusive tile scan -> g_offset / g_cursor. Coalesced.
__global__ void k_scanC(int n, int nblocks) {
    __shared__ int s_sums[MAX_SCAN_BLOCKS];
    __shared__ int s_warp[32];
    int t = threadIdx.x;
    int wid = t >> 5, lane = t & 31;
    int i = blockIdx.x * SCAN_BLK + t;

    if (t < MAX_SCAN_BLOCKS) s_sums[t] = (t < nblocks) ? g_blocksum[t] : 0;
    int v = (i < n) ? g_count[i] : 0;
    __syncthreads();

    // base for this block (broadcast LDS loop — all threads same address per iter)
    int base = 0;
    for (int j = 0; j < blockIdx.x; j++) base += s_sums[j];

    // warp inclusive scan
    int incl = v;
    #pragma unroll
    for (int o = 1; o < 32; o <<= 1) {
        int u = __shfl_up_sync(0xffffffffu, incl, o);
        if (lane >= o) incl += u;
    }
    if (lane == 31) s_warp[wid] = incl;
    __syncthreads();
    // prefix of earlier warps (broadcast LDS loop)
    int wpre = 0;
    for (int j = 0; j < wid; j++) wpre += s_warp[j];

    int excl = base + wpre + incl - v;
    if (i < n) {
        g_offset[i] = excl;
        g_cursor[i] = excl;
        if (i == n - 1) g_offset[n] = excl + v;   // total == E
    }
}

// Counting sort of edge sources by destination. int4-vectorized reads.
__global__ void k_scatter(const int* __restrict__ row, const int* __restrict__ col, int E4) {
    int i = blockIdx.x * blockDim.x + threadIdx.x;
    if (i < E4) {
        int4 r = reinterpret_cast<const int4*>(row)[i];
        int4 c = reinterpret_cast<const int4*>(col)[i];
        g_srow[atomicAdd(&g_cursor[c.x], 1)] = r.x;
        g_srow[atomicAdd(&g_cursor[c.y], 1)] = r.y;
        g_srow[atomicAdd(&g_cursor[c.z], 1)] = r.z;
        g_srow[atomicAdd(&g_cursor[c.w], 1)] = r.w;
    }
}

// One warp per destination node; lane handles features [2*lane, 2*lane+1].
// Atomic-free segmented mean; gathers are L2-resident. 4-deep accumulators.
__global__ void k_gather(const float* __restrict__ x, float* __restrict__ out, int n) {
    int warp = (blockIdx.x * blockDim.x + threadIdx.x) >> 5;
    int lane = threadIdx.x & 31;
    if (warp >= n) return;
    int start = g_offset[warp];
    int end   = g_offset[warp + 1];

    float2 a0 = make_float2(0.f, 0.f);
    float2 a1 = make_float2(0.f, 0.f);
    float2 a2 = make_float2(0.f, 0.f);
    float2 a3 = make_float2(0.f, 0.f);
    int i = start;
    for (; i + 4 <= end; i += 4) {
        int r0 = g_srow[i];
        int r1 = g_srow[i + 1];
        int r2 = g_srow[i + 2];
        int r3 = g_srow[i + 3];
        float2 v0 = *reinterpret_cast<const float2*>(x + ((size_t)r0 << 6) + (lane << 1));
        float2 v1 = *reinterpret_cast<const float2*>(x + ((size_t)r1 << 6) + (lane << 1));
        float2 v2 = *reinterpret_cast<const float2*>(x + ((size_t)r2 << 6) + (lane << 1));
        float2 v3 = *reinterpret_cast<const float2*>(x + ((size_t)r3 << 6) + (lane << 1));
        a0.x += v0.x; a0.y += v0.y;
        a1.x += v1.x; a1.y += v1.y;
        a2.x += v2.x; a2.y += v2.y;
        a3.x += v3.x; a3.y += v3.y;
    }
    for (; i < end; i++) {
        int r0 = g_srow[i];
        float2 v0 = *reinterpret_cast<const float2*>(x + ((size_t)r0 << 6) + (lane << 1));
        a0.x += v0.x; a0.y += v0.y;
    }
    int deg = end - start;
    float inv = 1.0f / (float)(deg > 0 ? deg : 1);
    float2 o = make_float2((a0.x + a1.x + a2.x + a3.x) * inv,
                           (a0.y + a1.y + a2.y + a3.y) * inv);
    *reinterpret_cast<float2*>(out + ((size_t)warp << 6) + (lane << 1)) = o;
}

extern "C" void kernel_launch(void* const* d_in, const int* in_sizes, int n_in,
                              void* d_out, int out_size) {
    const float* x    = (const float*)d_in[0];
    const int*   edge = (const int*)d_in[1];
    float*       out  = (float*)d_out;

    const int n  = in_sizes[0] / 64;    // 50000
    const int E  = in_sizes[1] / 2;     // 800000
    const int E4 = E / 4;               // 200000 (E % 4 == 0)
    const int n4 = MAX_NODES / 4;       // zero whole padded array
    const int* row = edge;              // edge_index[0, :]
    const int* col = edge + E;          // edge_index[1, :]

    const int nb_scan = (n + SCAN_BLK - 1) / SCAN_BLK;   // 49

    k_zero   <<<(n4 + 255) / 256, 256>>>(n4);
    k_hist   <<<(E4 + 255) / 256, 256>>>(col, E4);
    k_scanA  <<<nb_scan, SCAN_BLK>>>(n);
    k_scanC  <<<nb_scan, SCAN_BLK>>>(n, nb_scan);
    k_scatter<<<(E4 + 255) / 256, 256>>>(row, col, E4);
    k_gather <<<(n + 7) / 8, 256>>>(x, out, n);     // one warp per node
}